// round 4
// baseline (speedup 1.0000x reference)
#include <cuda_runtime.h>

#define N      64
#define L      8192
#define BATCH  2048
#define Q      64
#define CHUNKS 128
#define ZDIM   128
#define RTILE  16
#define TB     256
#define ZSTR   16                 // doubles per Z feature row (16 batch rows)
#define ZBUF   (ZDIM * ZSTR)      // u64 elems per Z buffer

// Fused per-chunk transition matrix P (ZDIM x ZDIM), row-major:
//   P[n][t]        = (C Ab^{t+1})[n]                  (Wout^T)
//   P[64+i][t]     = K[t-i] (i<=t) + D (i==t)         (lower-tri Toeplitz)
//   P[n][64+n']    = (Ab^64)[n'][n]                   (M^T)
//   P[64+i][64+n'] = (Ab^{63-i} Bb)[n']               (Win)
__device__ float  d_P[ZDIM * ZDIM];

// fp64 setup workspace
__device__ double d_T[N * N];      // I - (s/2)A
__device__ double d_R[N * N];      // I + (s/2)A
__device__ double d_X[N * N];      // inverse iterate (fp32 GJ seed)
__device__ double d_X2[N * N];
__device__ double d_E[N * N];
__device__ double d_Ab[N * N];
__device__ double d_SA[N * N];
__device__ double d_SB[N * N];
__device__ double d_Bvec[N];
__device__ double d_Cv[N];
__device__ double d_Dv;
__device__ double d_step;
__device__ double d_Rm[65][N];     // r_t = C Ab^t
__device__ double d_Cm[64][N];     // c_p = Ab^p Bb

// ---------------------------------------------------------------------------
// fp32 Gauss-Jordan (fast pipe) for approximate inverse; stash fp64 T, R.
// ---------------------------------------------------------------------------
__global__ void ssm_gj(const float* __restrict__ A, const float* __restrict__ B,
                       const float* __restrict__ C, const float* __restrict__ Dp,
                       const float* __restrict__ ls) {
    __shared__ float G[64 * 128];
    __shared__ float fac[64];
    const int tid = threadIdx.x, nt = 256;
    const double sd = exp((double)ls[0]);
    const float  s  = (float)sd;

    for (int idx = tid; idx < 64 * 64; idx += nt) {
        int i = idx >> 6, j = idx & 63;
        double a = (double)A[idx];
        d_T[idx] = (i == j ? 1.0 : 0.0) - 0.5 * sd * a;
        d_R[idx] = (i == j ? 1.0 : 0.0) + 0.5 * sd * a;
    }
    for (int idx = tid; idx < 64 * 128; idx += nt) {
        int i = idx >> 7, j = idx & 127;
        G[idx] = (j < 64) ? ((i == j ? 1.f : 0.f) - 0.5f * s * A[i * 64 + j])
                          : (((j - 64) == i) ? 1.f : 0.f);
    }
    if (tid < 64) { d_Cv[tid] = (double)C[tid]; d_Bvec[tid] = (double)B[tid]; }
    if (tid == 0) { d_Dv = (double)Dp[0]; d_step = sd; }
    __syncthreads();

    for (int p = 0; p < 64; ++p) {
        float pivinv = 1.f / G[p * 128 + p];
        __syncthreads();
        for (int j = tid; j < 128; j += nt) G[p * 128 + j] *= pivinv;
        for (int i = tid; i < 64;  i += nt) fac[i] = G[i * 128 + p];
        __syncthreads();
        for (int idx = tid; idx < 64 * 128; idx += nt) {
            int i = idx >> 7, j = idx & 127;
            if (i != p) G[idx] -= fac[i] * G[p * 128 + j];
        }
        __syncthreads();
    }
    for (int idx = tid; idx < 64 * 64; idx += nt) {
        int i = idx >> 6, j = idx & 63;
        d_X[idx] = (double)G[i * 128 + 64 + j];
    }
}

// fp64 64x64 matmul, one row per block.  mode 1: Out = I - A@B; mode 2: Out = A + A@B
__global__ void mm64(const double* __restrict__ A, const double* __restrict__ B,
                     double* __restrict__ Out, int mode) {
    __shared__ double ar[64];
    const int i = blockIdx.x, j = threadIdx.x;
    ar[j] = A[i * 64 + j];
    __syncthreads();
    double acc = 0.0;
    #pragma unroll 8
    for (int m = 0; m < 64; ++m) acc += ar[m] * B[m * 64 + j];
    if (mode == 1)      acc = ((i == j) ? 1.0 : 0.0) - acc;
    else if (mode == 2) acc += ar[j];
    Out[i * 64 + j] = acc;
}

// Ab = X@R (blocks 0..63), Bb = s*X@B (block 64); seeds Rm[0]=C, Cm[0]=Bb.
__global__ void ssm_abbb() {
    const int b = blockIdx.x, i = threadIdx.x;
    if (b < 64) {
        __shared__ double xr[64];
        xr[i] = d_X2[b * 64 + i];
        __syncthreads();
        double acc = 0.0;
        #pragma unroll 8
        for (int m = 0; m < 64; ++m) acc += xr[m] * d_R[m * 64 + i];
        d_Ab[b * 64 + i] = acc;
    } else {
        double acc = 0.0;
        for (int m = 0; m < 64; ++m) acc += d_X2[i * 64 + m] * d_Bvec[m];
        double bb = d_step * acc;
        d_Cm[0][i] = bb;
        d_Rm[0][i] = d_Cv[i];
    }
}

// Doubling level: extend Rm/Cm by 2^j entries with S = Ab^{2^j}; square S.
__global__ void ssm_level(int twoJ, const double* __restrict__ S,
                          double* __restrict__ Snext) {
    __shared__ double v[64];
    const int b = blockIdx.x, i = threadIdx.x;
    if (b < twoJ) {
        v[i] = d_Rm[b][i];
        __syncthreads();
        double acc = 0.0;
        #pragma unroll 8
        for (int m = 0; m < 64; ++m) acc += v[m] * S[m * 64 + i];
        d_Rm[b + twoJ][i] = acc;
    } else if (b < 2 * twoJ) {
        int p = b - twoJ;
        v[i] = d_Cm[p][i];
        __syncthreads();
        double acc = 0.0;
        #pragma unroll 8
        for (int m = 0; m < 64; ++m) acc += S[i * 64 + m] * v[m];
        d_Cm[p + twoJ][i] = acc;
    } else {
        int r = b - 2 * twoJ;
        v[i] = S[r * 64 + i];
        __syncthreads();
        double acc = 0.0;
        #pragma unroll 8
        for (int m = 0; m < 64; ++m) acc += v[m] * S[m * 64 + i];
        Snext[r * 64 + i] = acc;
    }
}

// Finalize: K dots, r_64 = C@M, fill fp32 P.
__global__ void ssm_fin() {
    __shared__ double Kk[64];
    __shared__ double r64[64];
    const int tid = threadIdx.x;      // 256
    const double* M = d_SB;           // Ab^64
    if (tid < 64) {
        double acc = 0.0;
        for (int m = 0; m < 64; ++m) acc += d_Cv[m] * d_Cm[tid][m];
        if (tid == 0) acc += d_Dv;
        Kk[tid] = acc;
    } else if (tid < 128) {
        int n = tid - 64;
        double acc = 0.0;
        for (int m = 0; m < 64; ++m) acc += d_Cv[m] * M[m * 64 + n];
        r64[n] = acc;
    }
    __syncthreads();
    for (int idx = tid; idx < ZDIM * ZDIM; idx += 256) {
        int i = idx >> 7, c = idx & 127;
        double v;
        if (i < 64) {
            if (c < 64) v = (c < 63) ? d_Rm[c + 1][i] : r64[i];
            else        v = M[(c - 64) * 64 + i];
        } else {
            int ii = i - 64;
            if (c < 64) v = (ii <= c) ? Kk[c - ii] : 0.0;
            else        v = d_Cm[63 - ii][c - 64];
        }
        d_P[idx] = (float)v;
    }
}

// ---------------------------------------------------------------------------
// Packed f32x2 helpers
// ---------------------------------------------------------------------------
__device__ __forceinline__ void ffma2(unsigned long long& acc,
                                      unsigned long long a, unsigned long long b) {
    asm("fma.rn.f32x2 %0, %1, %2, %0;" : "+l"(acc) : "l"(a), "l"(b));
}
__device__ __forceinline__ unsigned long long dup2(float v) {
    unsigned long long r;
    asm("mov.b64 %0, {%1, %1};" : "=l"(r) : "f"(v));
    return r;
}
__device__ __forceinline__ float2 unpk(unsigned long long p) {
    float2 f;
    asm("mov.b64 {%0, %1}, %2;" : "=f"(f.x), "=f"(f.y) : "l"(p));
    return f;
}

// ---------------------------------------------------------------------------
// Main: 128 CTAs x 256 threads (8 warps).  CTA owns 16 batch rows, walks 128
// chunks:  [Y | Xnew] = [X | U] @ P.
// Warp w owns output cols [16w, 16w+16) x all 16 rows; lane = 2 rows x 4 cols
// (rp = lane&7 -> rows {2rp, 2rp+1}; cg = lane>>3 -> cols 16w+4cg..+4).
// Per k: 1 LDS.128 (P), 1 LDS.128 (z row-pair), 4 FFMA2.  P traffic is 64KB
// per CTA per chunk (loaded once, not once per warp).
// Z is double-buffered (duplicated-f32 doubles, Zd[buf][k][r]); states + next
// U go to the write buffer -> exactly one __syncthreads per chunk.
// ---------------------------------------------------------------------------
__global__ void __launch_bounds__(TB, 1)
ssm_main(const float* __restrict__ u, float* __restrict__ y) {
    extern __shared__ float sm[];
    float* Ps = sm;                                                   // 128x128 f32
    unsigned long long* Zd =
        reinterpret_cast<unsigned long long*>(sm + ZDIM * ZDIM);      // 2 x [128][16]

    const int tid = threadIdx.x;
    const int w    = tid >> 5;
    const int lane = tid & 31;
    const int rp   = lane & 7;         // row pair -> rows 2rp, 2rp+1
    const int cg   = lane >> 3;        // col group
    const int c0   = w * 16 + cg * 4;  // global output col base
    const long rowBase = (long)blockIdx.x * RTILE;

    for (int i = tid; i < ZDIM * ZDIM; i += TB) Ps[i] = d_P[i];
    // zero state region of buffer 0
    for (int i = tid; i < 64 * ZSTR; i += TB) Zd[i] = 0ULL;

    // U staging map: thread -> (batch row rs, 4 consecutive taus)
    const int rs = tid >> 4, tau4 = (tid & 15) * 4;
    const float* urow = u + (rowBase + rs) * L + tau4;
    unsigned long long* zsU0 = Zd + (64 + tau4) * ZSTR + rs;          // buffer 0

    // stage chunk 0 into buffer 0
    {
        float4 p0 = *reinterpret_cast<const float4*>(urow);
        zsU0[0 * ZSTR] = dup2(p0.x); zsU0[1 * ZSTR] = dup2(p0.y);
        zsU0[2 * ZSTR] = dup2(p0.z); zsU0[3 * ZSTR] = dup2(p0.w);
    }
    __syncthreads();

    const bool isY = (c0 < Q);
    float* yb0 = y + (rowBase + 2 * rp) * L + c0;
    const int cc = c0 - 64;
    const float* pP = Ps + c0;

    float4 pre = (CHUNKS > 1) ? *reinterpret_cast<const float4*>(urow + Q)
                              : make_float4(0.f, 0.f, 0.f, 0.f);

    for (int j = 0; j < CHUNKS; ++j) {
        const int rb = j & 1, wb = rb ^ 1;
        const unsigned long long* zb = Zd + rb * ZBUF + 2 * rp;
        unsigned long long*       zw = Zd + wb * ZBUF;

        unsigned long long a00 = 0, a01 = 0, a10 = 0, a11 = 0;
        #pragma unroll 16
        for (int k = 0; k < ZDIM; ++k) {
            ulonglong2 p2 = *reinterpret_cast<const ulonglong2*>(pP + k * ZDIM);
            ulonglong2 zz = *reinterpret_cast<const ulonglong2*>(zb + k * ZSTR);
            ffma2(a00, p2.x, zz.x); ffma2(a01, p2.y, zz.x);
            ffma2(a10, p2.x, zz.y); ffma2(a11, p2.y, zz.y);
        }

        if (isY) {
            *reinterpret_cast<ulonglong2*>(yb0 + (long)j * Q)     = make_ulonglong2(a00, a01);
            *reinterpret_cast<ulonglong2*>(yb0 + (long)j * Q + L) = make_ulonglong2(a10, a11);
        } else {
            float2 f0 = unpk(a00), f1 = unpk(a10);   // cols cc, cc+1
            float2 g0 = unpk(a01), g1 = unpk(a11);   // cols cc+2, cc+3
            *reinterpret_cast<ulonglong2*>(zw + (cc + 0) * ZSTR + 2 * rp) =
                make_ulonglong2(dup2(f0.x), dup2(f1.x));
            *reinterpret_cast<ulonglong2*>(zw + (cc + 1) * ZSTR + 2 * rp) =
                make_ulonglong2(dup2(f0.y), dup2(f1.y));
            *reinterpret_cast<ulonglong2*>(zw + (cc + 2) * ZSTR + 2 * rp) =
                make_ulonglong2(dup2(g0.x), dup2(g1.x));
            *reinterpret_cast<ulonglong2*>(zw + (cc + 3) * ZSTR + 2 * rp) =
                make_ulonglong2(dup2(g0.y), dup2(g1.y));
        }

        if (j + 1 < CHUNKS) {
            // stage prefetched chunk j+1 U into write buffer
            unsigned long long* zsU = zw + (64 + tau4) * ZSTR + rs;
            zsU[0 * ZSTR] = dup2(pre.x); zsU[1 * ZSTR] = dup2(pre.y);
            zsU[2 * ZSTR] = dup2(pre.z); zsU[3 * ZSTR] = dup2(pre.w);
            if (j + 2 < CHUNKS)
                pre = *reinterpret_cast<const float4*>(urow + (long)(j + 2) * Q);
        }
        __syncthreads();
    }
}

extern "C" void kernel_launch(void* const* d_in, const int* in_sizes, int n_in,
                              void* d_out, int out_size) {
    const float* u  = (const float*)d_in[0];
    const float* A  = (const float*)d_in[1];
    const float* B  = (const float*)d_in[2];
    const float* C  = (const float*)d_in[3];
    const float* D  = (const float*)d_in[4];
    const float* ls = (const float*)d_in[5];
    float* y = (float*)d_out;

    double *pT, *pX, *pX2, *pE, *pAb, *pSA, *pSB;
    cudaGetSymbolAddress((void**)&pT,  d_T);
    cudaGetSymbolAddress((void**)&pX,  d_X);
    cudaGetSymbolAddress((void**)&pX2, d_X2);
    cudaGetSymbolAddress((void**)&pE,  d_E);
    cudaGetSymbolAddress((void**)&pAb, d_Ab);
    cudaGetSymbolAddress((void**)&pSA, d_SA);
    cudaGetSymbolAddress((void**)&pSB, d_SB);

    const int smemMain = ZDIM * ZDIM * 4 + 2 * ZBUF * 8;   // 64KB + 32KB = 98304 B
    cudaFuncSetAttribute(ssm_main, cudaFuncAttributeMaxDynamicSharedMemorySize, smemMain);

    ssm_gj<<<1, 256>>>(A, B, C, D, ls);
    // One fp64 Newton iteration: X2 = X + X(I - T X)  (fp32-GJ err ~4e-6 -> ~2e-11)
    mm64<<<64, 64>>>(pT, pX, pE,  1);
    mm64<<<64, 64>>>(pX, pE, pX2, 2);
    ssm_abbb<<<65, 64>>>();

    // Doubling levels: chain extension + squaring fused.
    const double* Sptr[6]  = {pAb, pSA, pSB, pSA, pSB, pSA};
    double*       Snext[6] = {pSA, pSB, pSA, pSB, pSA, pSB};   // level 5 -> SB = Ab^64
    for (int j = 0; j < 6; ++j) {
        int twoJ = 1 << j;
        ssm_level<<<2 * twoJ + 64, 64>>>(twoJ, Sptr[j], Snext[j]);
    }
    ssm_fin<<<1, 256>>>();

    ssm_main<<<BATCH / RTILE, TB, smemMain>>>(u, y);
}

// round 5
// speedup vs baseline: 1.0017x; 1.0017x over previous
#include <cuda_runtime.h>

#define N      64
#define L      8192
#define BATCH  2048
#define Q      64
#define CHUNKS 128
#define ZDIM   128
#define RTILE  16
#define TB     256
#define ZSTR   16                 // doubles per Z feature row (16 batch rows)
#define ZBUF   (ZDIM * ZSTR)      // u64 elems per Z buffer

// Fused per-chunk transition matrix P (ZDIM x ZDIM), row-major:
//   P[n][t]        = (C Ab^{t+1})[n]                  (Wout^T)
//   P[64+i][t]     = K[t-i] (i<=t) + D (i==t)         (lower-tri Toeplitz)
//   P[n][64+n']    = (Ab^64)[n'][n]                   (M^T)
//   P[64+i][64+n'] = (Ab^{63-i} Bb)[n']               (Win)
__device__ float  d_P[ZDIM * ZDIM];

// fp64 setup workspace
__device__ double d_T[N * N];      // I - (s/2)A
__device__ double d_R[N * N];      // I + (s/2)A
__device__ double d_X[N * N];      // inverse iterate (fp32 GJ seed)
__device__ double d_X2[N * N];
__device__ double d_E[N * N];
__device__ double d_Ab[N * N];
__device__ double d_SA[N * N];
__device__ double d_SB[N * N];
__device__ double d_Bvec[N];
__device__ double d_Cv[N];
__device__ double d_Dv;
__device__ double d_step;
__device__ double d_Rm[65][N];     // r_t = C Ab^t
__device__ double d_Cm[64][N];     // c_p = Ab^p Bb

// ---------------------------------------------------------------------------
// fp32 Gauss-Jordan (fast pipe) for approximate inverse; stash fp64 T, R.
// ---------------------------------------------------------------------------
__global__ void ssm_gj(const float* __restrict__ A, const float* __restrict__ B,
                       const float* __restrict__ C, const float* __restrict__ Dp,
                       const float* __restrict__ ls) {
    __shared__ float G[64 * 128];
    __shared__ float fac[64];
    const int tid = threadIdx.x, nt = 256;
    const double sd = exp((double)ls[0]);
    const float  s  = (float)sd;

    for (int idx = tid; idx < 64 * 64; idx += nt) {
        int i = idx >> 6, j = idx & 63;
        double a = (double)A[idx];
        d_T[idx] = (i == j ? 1.0 : 0.0) - 0.5 * sd * a;
        d_R[idx] = (i == j ? 1.0 : 0.0) + 0.5 * sd * a;
    }
    for (int idx = tid; idx < 64 * 128; idx += nt) {
        int i = idx >> 7, j = idx & 127;
        G[idx] = (j < 64) ? ((i == j ? 1.f : 0.f) - 0.5f * s * A[i * 64 + j])
                          : (((j - 64) == i) ? 1.f : 0.f);
    }
    if (tid < 64) { d_Cv[tid] = (double)C[tid]; d_Bvec[tid] = (double)B[tid]; }
    if (tid == 0) { d_Dv = (double)Dp[0]; d_step = sd; }
    __syncthreads();

    for (int p = 0; p < 64; ++p) {
        float pivinv = 1.f / G[p * 128 + p];
        __syncthreads();
        for (int j = tid; j < 128; j += nt) G[p * 128 + j] *= pivinv;
        for (int i = tid; i < 64;  i += nt) fac[i] = G[i * 128 + p];
        __syncthreads();
        for (int idx = tid; idx < 64 * 128; idx += nt) {
            int i = idx >> 7, j = idx & 127;
            if (i != p) G[idx] -= fac[i] * G[p * 128 + j];
        }
        __syncthreads();
    }
    for (int idx = tid; idx < 64 * 64; idx += nt) {
        int i = idx >> 6, j = idx & 63;
        d_X[idx] = (double)G[i * 128 + 64 + j];
    }
}

// fp64 64x64 matmul, one row per block.  mode 1: Out = I - A@B; mode 2: Out = A + A@B
__global__ void mm64(const double* __restrict__ A, const double* __restrict__ B,
                     double* __restrict__ Out, int mode) {
    __shared__ double ar[64];
    const int i = blockIdx.x, j = threadIdx.x;
    ar[j] = A[i * 64 + j];
    __syncthreads();
    double acc = 0.0;
    #pragma unroll 8
    for (int m = 0; m < 64; ++m) acc += ar[m] * B[m * 64 + j];
    if (mode == 1)      acc = ((i == j) ? 1.0 : 0.0) - acc;
    else if (mode == 2) acc += ar[j];
    Out[i * 64 + j] = acc;
}

// Ab = X@R (blocks 0..63), Bb = s*X@B (block 64); seeds Rm[0]=C, Cm[0]=Bb.
__global__ void ssm_abbb() {
    const int b = blockIdx.x, i = threadIdx.x;
    if (b < 64) {
        __shared__ double xr[64];
        xr[i] = d_X2[b * 64 + i];
        __syncthreads();
        double acc = 0.0;
        #pragma unroll 8
        for (int m = 0; m < 64; ++m) acc += xr[m] * d_R[m * 64 + i];
        d_Ab[b * 64 + i] = acc;
    } else {
        double acc = 0.0;
        for (int m = 0; m < 64; ++m) acc += d_X2[i * 64 + m] * d_Bvec[m];
        double bb = d_step * acc;
        d_Cm[0][i] = bb;
        d_Rm[0][i] = d_Cv[i];
    }
}

// Doubling level: extend Rm/Cm by 2^j entries with S = Ab^{2^j}; square S.
__global__ void ssm_level(int twoJ, const double* __restrict__ S,
                          double* __restrict__ Snext) {
    __shared__ double v[64];
    const int b = blockIdx.x, i = threadIdx.x;
    if (b < twoJ) {
        v[i] = d_Rm[b][i];
        __syncthreads();
        double acc = 0.0;
        #pragma unroll 8
        for (int m = 0; m < 64; ++m) acc += v[m] * S[m * 64 + i];
        d_Rm[b + twoJ][i] = acc;
    } else if (b < 2 * twoJ) {
        int p = b - twoJ;
        v[i] = d_Cm[p][i];
        __syncthreads();
        double acc = 0.0;
        #pragma unroll 8
        for (int m = 0; m < 64; ++m) acc += S[i * 64 + m] * v[m];
        d_Cm[p + twoJ][i] = acc;
    } else {
        int r = b - 2 * twoJ;
        v[i] = S[r * 64 + i];
        __syncthreads();
        double acc = 0.0;
        #pragma unroll 8
        for (int m = 0; m < 64; ++m) acc += v[m] * S[m * 64 + i];
        Snext[r * 64 + i] = acc;
    }
}

// Finalize: K dots, r_64 = C@M, fill fp32 P.
__global__ void ssm_fin() {
    __shared__ double Kk[64];
    __shared__ double r64[64];
    const int tid = threadIdx.x;      // 256
    const double* M = d_SB;           // Ab^64
    if (tid < 64) {
        double acc = 0.0;
        for (int m = 0; m < 64; ++m) acc += d_Cv[m] * d_Cm[tid][m];
        if (tid == 0) acc += d_Dv;
        Kk[tid] = acc;
    } else if (tid < 128) {
        int n = tid - 64;
        double acc = 0.0;
        for (int m = 0; m < 64; ++m) acc += d_Cv[m] * M[m * 64 + n];
        r64[n] = acc;
    }
    __syncthreads();
    for (int idx = tid; idx < ZDIM * ZDIM; idx += 256) {
        int i = idx >> 7, c = idx & 127;
        double v;
        if (i < 64) {
            if (c < 64) v = (c < 63) ? d_Rm[c + 1][i] : r64[i];
            else        v = M[(c - 64) * 64 + i];
        } else {
            int ii = i - 64;
            if (c < 64) v = (ii <= c) ? Kk[c - ii] : 0.0;
            else        v = d_Cm[63 - ii][c - 64];
        }
        d_P[idx] = (float)v;
    }
}

// ---------------------------------------------------------------------------
// Packed f32x2 helpers
// ---------------------------------------------------------------------------
__device__ __forceinline__ void ffma2(unsigned long long& acc,
                                      unsigned long long a, unsigned long long b) {
    asm("fma.rn.f32x2 %0, %1, %2, %0;" : "+l"(acc) : "l"(a), "l"(b));
}
__device__ __forceinline__ unsigned long long dup2(float v) {
    unsigned long long r;
    asm("mov.b64 %0, {%1, %1};" : "=l"(r) : "f"(v));
    return r;
}
__device__ __forceinline__ float2 unpk(unsigned long long p) {
    float2 f;
    asm("mov.b64 {%0, %1}, %2;" : "=f"(f.x), "=f"(f.y) : "l"(p));
    return f;
}

// ---------------------------------------------------------------------------
// Main: 128 CTAs x 256 threads (8 warps).  CTA owns 16 batch rows, walks 128
// chunks:  [Y | Xnew] = [X | U] @ P.
// Warp w owns output cols [16w, 16w+16) x all 16 rows; lane = 2 rows x 4 cols
// (rp = lane&7 -> rows {2rp, 2rp+1}; cg = lane>>3 -> cols 16w+4cg..+4).
// Per k: 1 LDS.128 (P), 1 LDS.128 (z row-pair), 4 FFMA2.  P traffic is 64KB
// per CTA per chunk (loaded once, not once per warp).
// Z is double-buffered (duplicated-f32 doubles, Zd[buf][k][r]); states + next
// U go to the write buffer -> exactly one __syncthreads per chunk.
// ---------------------------------------------------------------------------
__global__ void __launch_bounds__(TB, 1)
ssm_main(const float* __restrict__ u, float* __restrict__ y) {
    extern __shared__ float sm[];
    float* Ps = sm;                                                   // 128x128 f32
    unsigned long long* Zd =
        reinterpret_cast<unsigned long long*>(sm + ZDIM * ZDIM);      // 2 x [128][16]

    const int tid = threadIdx.x;
    const int w    = tid >> 5;
    const int lane = tid & 31;
    const int rp   = lane & 7;         // row pair -> rows 2rp, 2rp+1
    const int cg   = lane >> 3;        // col group
    const int c0   = w * 16 + cg * 4;  // global output col base
    const long rowBase = (long)blockIdx.x * RTILE;

    for (int i = tid; i < ZDIM * ZDIM; i += TB) Ps[i] = d_P[i];
    // zero state region of buffer 0
    for (int i = tid; i < 64 * ZSTR; i += TB) Zd[i] = 0ULL;

    // U staging map: thread -> (batch row rs, 4 consecutive taus)
    const int rs = tid >> 4, tau4 = (tid & 15) * 4;
    const float* urow = u + (rowBase + rs) * L + tau4;
    unsigned long long* zsU0 = Zd + (64 + tau4) * ZSTR + rs;          // buffer 0

    // stage chunk 0 into buffer 0
    {
        float4 p0 = *reinterpret_cast<const float4*>(urow);
        zsU0[0 * ZSTR] = dup2(p0.x); zsU0[1 * ZSTR] = dup2(p0.y);
        zsU0[2 * ZSTR] = dup2(p0.z); zsU0[3 * ZSTR] = dup2(p0.w);
    }
    __syncthreads();

    const bool isY = (c0 < Q);
    float* yb0 = y + (rowBase + 2 * rp) * L + c0;
    const int cc = c0 - 64;
    const float* pP = Ps + c0;

    float4 pre = (CHUNKS > 1) ? *reinterpret_cast<const float4*>(urow + Q)
                              : make_float4(0.f, 0.f, 0.f, 0.f);

    for (int j = 0; j < CHUNKS; ++j) {
        const int rb = j & 1, wb = rb ^ 1;
        const unsigned long long* zb = Zd + rb * ZBUF + 2 * rp;
        unsigned long long*       zw = Zd + wb * ZBUF;

        unsigned long long a00 = 0, a01 = 0, a10 = 0, a11 = 0;
        #pragma unroll 16
        for (int k = 0; k < ZDIM; ++k) {
            ulonglong2 p2 = *reinterpret_cast<const ulonglong2*>(pP + k * ZDIM);
            ulonglong2 zz = *reinterpret_cast<const ulonglong2*>(zb + k * ZSTR);
            ffma2(a00, p2.x, zz.x); ffma2(a01, p2.y, zz.x);
            ffma2(a10, p2.x, zz.y); ffma2(a11, p2.y, zz.y);
        }

        if (isY) {
            *reinterpret_cast<ulonglong2*>(yb0 + (long)j * Q)     = make_ulonglong2(a00, a01);
            *reinterpret_cast<ulonglong2*>(yb0 + (long)j * Q + L) = make_ulonglong2(a10, a11);
        } else {
            float2 f0 = unpk(a00), f1 = unpk(a10);   // cols cc, cc+1
            float2 g0 = unpk(a01), g1 = unpk(a11);   // cols cc+2, cc+3
            *reinterpret_cast<ulonglong2*>(zw + (cc + 0) * ZSTR + 2 * rp) =
                make_ulonglong2(dup2(f0.x), dup2(f1.x));
            *reinterpret_cast<ulonglong2*>(zw + (cc + 1) * ZSTR + 2 * rp) =
                make_ulonglong2(dup2(f0.y), dup2(f1.y));
            *reinterpret_cast<ulonglong2*>(zw + (cc + 2) * ZSTR + 2 * rp) =
                make_ulonglong2(dup2(g0.x), dup2(g1.x));
            *reinterpret_cast<ulonglong2*>(zw + (cc + 3) * ZSTR + 2 * rp) =
                make_ulonglong2(dup2(g0.y), dup2(g1.y));
        }

        if (j + 1 < CHUNKS) {
            // stage prefetched chunk j+1 U into write buffer
            unsigned long long* zsU = zw + (64 + tau4) * ZSTR + rs;
            zsU[0 * ZSTR] = dup2(pre.x); zsU[1 * ZSTR] = dup2(pre.y);
            zsU[2 * ZSTR] = dup2(pre.z); zsU[3 * ZSTR] = dup2(pre.w);
            if (j + 2 < CHUNKS)
                pre = *reinterpret_cast<const float4*>(urow + (long)(j + 2) * Q);
        }
        __syncthreads();
    }
}

extern "C" void kernel_launch(void* const* d_in, const int* in_sizes, int n_in,
                              void* d_out, int out_size) {
    const float* u  = (const float*)d_in[0];
    const float* A  = (const float*)d_in[1];
    const float* B  = (const float*)d_in[2];
    const float* C  = (const float*)d_in[3];
    const float* D  = (const float*)d_in[4];
    const float* ls = (const float*)d_in[5];
    float* y = (float*)d_out;

    double *pT, *pX, *pX2, *pE, *pAb, *pSA, *pSB;
    cudaGetSymbolAddress((void**)&pT,  d_T);
    cudaGetSymbolAddress((void**)&pX,  d_X);
    cudaGetSymbolAddress((void**)&pX2, d_X2);
    cudaGetSymbolAddress((void**)&pE,  d_E);
    cudaGetSymbolAddress((void**)&pAb, d_Ab);
    cudaGetSymbolAddress((void**)&pSA, d_SA);
    cudaGetSymbolAddress((void**)&pSB, d_SB);

    const int smemMain = ZDIM * ZDIM * 4 + 2 * ZBUF * 8;   // 64KB + 32KB = 98304 B
    cudaFuncSetAttribute(ssm_main, cudaFuncAttributeMaxDynamicSharedMemorySize, smemMain);

    ssm_gj<<<1, 256>>>(A, B, C, D, ls);
    // One fp64 Newton iteration: X2 = X + X(I - T X)  (fp32-GJ err ~4e-6 -> ~2e-11)
    mm64<<<64, 64>>>(pT, pX, pE,  1);
    mm64<<<64, 64>>>(pX, pE, pX2, 2);
    ssm_abbb<<<65, 64>>>();

    // Doubling levels: chain extension + squaring fused.
    const double* Sptr[6]  = {pAb, pSA, pSB, pSA, pSB, pSA};
    double*       Snext[6] = {pSA, pSB, pSA, pSB, pSA, pSB};   // level 5 -> SB = Ab^64
    for (int j = 0; j < 6; ++j) {
        int twoJ = 1 << j;
        ssm_level<<<2 * twoJ + 64, 64>>>(twoJ, Sptr[j], Snext[j]);
    }
    ssm_fin<<<1, 256>>>();

    ssm_main<<<BATCH / RTILE, TB, smemMain>>>(u, y);
}

// round 7
// speedup vs baseline: 1.6561x; 1.6533x over previous
#include <cuda_runtime.h>
#include <cuda_bf16.h>
#include <cstdint>

#define NB    64          // state size
#define L     8192
#define BATCH 2048
#define QC    128         // chunk length
#define NCH   64          // chunks
#define KB    192         // 64 (X) + 128 (U)

// ---------------- constants built by setup ----------------
__device__ float d_Mf[NB * NB];                               // Ab^128
__device__ __nv_bfloat16 d_WHi[NB * QC],  d_WLo[NB * QC];     // WinT [n][i], pitch 128
__device__ __nv_bfloat16 d_PbHi[QC * KB], d_PbLo[QC * KB];    // PbT  [t][k], pitch 192
__device__ float d_V  [(size_t)NCH * BATCH * NB];             // V[j][b][n]
__device__ float d_Xst[(size_t)NCH * BATCH * NB];             // X[j][b][n]

// fp64 setup workspace
__device__ double d_T[NB * NB], d_R[NB * NB], d_X[NB * NB], d_X2[NB * NB];
__device__ double d_W[NB * NB], d_Ab[NB * NB], d_SA[NB * NB], d_SB[NB * NB];
__device__ double d_Rm[QC + 1][NB], d_Cm[QC][NB], d_Kk[QC];
__device__ double d_Cv[NB], d_Bv[NB], d_Dv, d_sp;
__device__ unsigned g_cnt = 0;
__device__ volatile unsigned g_gen = 0;

// ---------------- helpers ----------------
__device__ __forceinline__ void splitpk(float a, float b, uint32_t& hi, uint32_t& lo) {
    __nv_bfloat16 ha = __float2bfloat16(a), hb = __float2bfloat16(b);
    __nv_bfloat162 h, l;
    h.x = ha; h.y = hb;
    l.x = __float2bfloat16(a - __bfloat162float(ha));
    l.y = __float2bfloat16(b - __bfloat162float(hb));
    hi = *(uint32_t*)&h; lo = *(uint32_t*)&l;
}
__device__ __forceinline__ void mma16816(float* c, uint32_t a0, uint32_t a1,
                                         uint32_t a2, uint32_t a3,
                                         uint32_t b0, uint32_t b1) {
    asm volatile(
        "mma.sync.aligned.m16n8k16.row.col.f32.bf16.bf16.f32 "
        "{%0,%1,%2,%3}, {%4,%5,%6,%7}, {%8,%9}, {%0,%1,%2,%3};"
        : "+f"(c[0]), "+f"(c[1]), "+f"(c[2]), "+f"(c[3])
        : "r"(a0), "r"(a1), "r"(a2), "r"(a3), "r"(b0), "r"(b1));
}

// ---------------- L0: fp32 Gauss-Jordan seed + fp64 stash ----------------
__global__ void ssm_gj(const float* __restrict__ A, const float* __restrict__ B,
                       const float* __restrict__ C, const float* __restrict__ Dp,
                       const float* __restrict__ ls) {
    __shared__ float G[64 * 128];
    __shared__ float fac[64];
    const int tid = threadIdx.x, nt = 256;
    const double sd = exp((double)ls[0]);
    const float s = (float)sd;
    for (int i = tid; i < 4096; i += nt) {
        int r = i >> 6, c = i & 63;
        double a = (double)A[i];
        d_T[i] = (r == c ? 1.0 : 0.0) - 0.5 * sd * a;
        d_R[i] = (r == c ? 1.0 : 0.0) + 0.5 * sd * a;
    }
    for (int i = tid; i < 8192; i += nt) {
        int r = i >> 7, c = i & 127;
        G[i] = (c < 64) ? ((r == c ? 1.f : 0.f) - 0.5f * s * A[r * 64 + c])
                        : (((c - 64) == r) ? 1.f : 0.f);
    }
    if (tid < 64) { d_Cv[tid] = (double)C[tid]; d_Bv[tid] = (double)B[tid]; }
    if (tid == 0) { d_Dv = (double)Dp[0]; d_sp = sd; }
    __syncthreads();
    for (int p = 0; p < 64; ++p) {
        float pv = 1.f / G[p * 128 + p];
        __syncthreads();
        for (int c = tid; c < 128; c += nt) G[p * 128 + c] *= pv;
        for (int r = tid; r < 64; r += nt) fac[r] = G[r * 128 + p];
        __syncthreads();
        for (int i = tid; i < 8192; i += nt) {
            int r = i >> 7, c = i & 127;
            if (r != p) G[i] -= fac[r] * G[p * 128 + c];
        }
        __syncthreads();
    }
    for (int i = tid; i < 4096; i += nt)
        d_X[i] = (double)G[(i >> 6) * 128 + 64 + (i & 63)];
}

// ---------------- L1: mega setup (192 blocks x 64, grid barrier) ----------
__device__ __forceinline__ void gbar() {
    __syncthreads();
    if (threadIdx.x == 0) {
        __threadfence();
        unsigned g = g_gen;
        if (atomicAdd(&g_cnt, 1u) == 191u) { g_cnt = 0; __threadfence(); g_gen = g + 1; }
        else { while (g_gen == g) __nanosleep(64); __threadfence(); }
    }
    __syncthreads();
}
__global__ void ssm_mega() {
    __shared__ double v[64], red[64];
    const int b = blockIdx.x, t = threadIdx.x;
    if (b < 64) {                                  // W = X*T
        v[t] = d_X[b * 64 + t]; __syncthreads();
        double a = 0; for (int m = 0; m < 64; ++m) a += v[m] * d_T[m * 64 + t];
        d_W[b * 64 + t] = a;
    }
    gbar();
    if (b < 64) {                                  // X2 = 2X - W*X  (Newton)
        v[t] = d_W[b * 64 + t]; __syncthreads();
        double a = 0; for (int m = 0; m < 64; ++m) a += v[m] * d_X[m * 64 + t];
        d_X2[b * 64 + t] = 2.0 * d_X[b * 64 + t] - a;
    }
    gbar();
    if (b < 64) {                                  // Ab = X2*R
        v[t] = d_X2[b * 64 + t]; __syncthreads();
        double a = 0; for (int m = 0; m < 64; ++m) a += v[m] * d_R[m * 64 + t];
        d_Ab[b * 64 + t] = a;
    } else if (b == 64) {                          // Bb; seeds
        double a = 0; for (int m = 0; m < 64; ++m) a += d_X2[t * 64 + m] * d_Bv[m];
        d_Cm[0][t] = d_sp * a; d_Rm[0][t] = d_Cv[t];
    }
    gbar();
    for (int lev = 0; lev < 7; ++lev) {            // chains + squaring to Ab^128
        int tw = 1 << lev;
        const double* S = (lev == 0) ? d_Ab : ((lev & 1) ? d_SA : d_SB);
        double* Sd = (lev & 1) ? d_SB : d_SA;
        if (b < tw) {                              // r_{t+tw} = r_t S
            v[t] = d_Rm[b][t]; __syncthreads();
            double a = 0; for (int m = 0; m < 64; ++m) a += v[m] * S[m * 64 + t];
            d_Rm[b + tw][t] = a;
        } else if (b < 2 * tw) {                   // c_{p+tw} = S c_p
            v[t] = d_Cm[b - tw][t]; __syncthreads();
            double a = 0; for (int m = 0; m < 64; ++m) a += S[t * 64 + m] * v[m];
            d_Cm[b][t] = a;
        } else if (b < 2 * tw + 64) {              // S' = S*S
            int r = b - 2 * tw;
            v[t] = S[r * 64 + t]; __syncthreads();
            double a = 0; for (int m = 0; m < 64; ++m) a += v[m] * S[m * 64 + t];
            Sd[r * 64 + t] = a;
        }
        gbar();
    }
    // M = Ab^128 lives in d_SA
    if (b < QC) {                                  // Kk[b] = C . c_b  (+D at 0)
        red[t] = d_Cv[t] * d_Cm[b][t]; __syncthreads();
        for (int o = 32; o > 0; o >>= 1) { if (t < o) red[t] += red[t + o]; __syncthreads(); }
        if (t == 0) d_Kk[b] = red[0] + ((b == 0) ? d_Dv : 0.0);
    } else if (b == QC) {                          // r_128 = C * M
        double a = 0; for (int m = 0; m < 64; ++m) a += d_Cv[m] * d_SA[m * 64 + t];
        d_Rm[QC][t] = a;
    }
    gbar();
    const int gt = b * 64 + t, NT = 192 * 64;      // fills
    for (int i = gt; i < 4096; i += NT) d_Mf[i] = (float)d_SA[i];
    for (int i = gt; i < NB * QC; i += NT) {       // WinT[n][ii] = c_{127-ii}[n]
        int n = i >> 7, ii = i & 127;
        float f = (float)d_Cm[QC - 1 - ii][n];
        __nv_bfloat16 h = __float2bfloat16(f);
        d_WHi[i] = h; d_WLo[i] = __float2bfloat16(f - __bfloat162float(h));
    }
    for (int i = gt; i < QC * KB; i += NT) {       // PbT[t][k]
        int tt = i / KB, k = i % KB;
        double dv;
        if (k < 64) dv = d_Rm[tt + 1][k];
        else { int ii = k - 64; dv = (ii <= tt) ? d_Kk[tt - ii] : 0.0; }
        float f = (float)dv;
        __nv_bfloat16 h = __float2bfloat16(f);
        d_PbHi[i] = h; d_PbLo[i] = __float2bfloat16(f - __bfloat162float(h));
    }
}

// ---------------- A0: V = U * Win  (1024 CTAs x 256, HMMA) -----------------
// smem (bf16 units): AH 128x72, AL 128x72, BH 64x72, BL 64x72
#define A0_AH 0
#define A0_AL 9216
#define A0_BH 18432
#define A0_BL 23040
__global__ void __launch_bounds__(256) ssm_a0(const float* __restrict__ u) {
    extern __shared__ __align__(16) __nv_bfloat16 smb[];
    uint32_t* sw = reinterpret_cast<uint32_t*>(smb);
    const int tid = threadIdx.x;
    const int j = blockIdx.x >> 4, b0 = (blockIdx.x & 15) << 7;
    const int wid = tid >> 5, lane = tid & 31;
    const int g = lane >> 2, tq = lane & 3;
    const int wm = wid >> 1, wn = wid & 1;          // 4x2 warp grid
    const int RM = wm * 32, CN = wn * 32;

    float acc[2][4][4];
    #pragma unroll
    for (int a = 0; a < 2; ++a)
        #pragma unroll
        for (int bq = 0; bq < 4; ++bq)
            #pragma unroll
            for (int cq = 0; cq < 4; ++cq) acc[a][bq][cq] = 0.f;

    for (int s = 0; s < 2; ++s) {
        // stage Win slab: 64 n rows x 32 u32
        for (int i = tid; i < 2048; i += 256) {
            int n = i >> 5, c2 = i & 31;
            sw[(A0_BH >> 1) + n * 36 + c2] = ((const uint32_t*)d_WHi)[n * 64 + s * 32 + c2];
            sw[(A0_BL >> 1) + n * 36 + c2] = ((const uint32_t*)d_WLo)[n * 64 + s * 32 + c2];
        }
        // stage U slab hi/lo: 128 rows x 64 floats
        for (int i = tid; i < 2048; i += 256) {
            int r = i >> 4, c4 = (i & 15) * 4;
            float4 f = *(const float4*)(u + (size_t)(b0 + r) * L + j * QC + s * 64 + c4);
            uint32_t h0, l0, h1, l1;
            splitpk(f.x, f.y, h0, l0); splitpk(f.z, f.w, h1, l1);
            int o = r * 36 + (c4 >> 1);
            sw[(A0_AH >> 1) + o] = h0; sw[(A0_AH >> 1) + o + 1] = h1;
            sw[(A0_AL >> 1) + o] = l0; sw[(A0_AL >> 1) + o + 1] = l1;
        }
        __syncthreads();
        #pragma unroll
        for (int kk = 0; kk < 64; kk += 16) {
            const int kb = (kk >> 1) + tq;
            uint32_t bh0[4], bh1[4], bl0[4], bl1[4];
            #pragma unroll
            for (int nt = 0; nt < 4; ++nt) {
                int n = CN + nt * 8 + g;
                bh0[nt] = sw[(A0_BH >> 1) + n * 36 + kb];
                bh1[nt] = sw[(A0_BH >> 1) + n * 36 + kb + 4];
                bl0[nt] = sw[(A0_BL >> 1) + n * 36 + kb];
                bl1[nt] = sw[(A0_BL >> 1) + n * 36 + kb + 4];
            }
            #pragma unroll
            for (int mt = 0; mt < 2; ++mt) {
                int r0 = RM + mt * 16 + g, r1 = r0 + 8;
                uint32_t ah0 = sw[(A0_AH >> 1) + r0 * 36 + kb];
                uint32_t ah1 = sw[(A0_AH >> 1) + r1 * 36 + kb];
                uint32_t ah2 = sw[(A0_AH >> 1) + r0 * 36 + kb + 4];
                uint32_t ah3 = sw[(A0_AH >> 1) + r1 * 36 + kb + 4];
                uint32_t al0 = sw[(A0_AL >> 1) + r0 * 36 + kb];
                uint32_t al1 = sw[(A0_AL >> 1) + r1 * 36 + kb];
                uint32_t al2 = sw[(A0_AL >> 1) + r0 * 36 + kb + 4];
                uint32_t al3 = sw[(A0_AL >> 1) + r1 * 36 + kb + 4];
                #pragma unroll
                for (int nt = 0; nt < 4; ++nt) {
                    mma16816(acc[mt][nt], ah0, ah1, ah2, ah3, bh0[nt], bh1[nt]);
                    mma16816(acc[mt][nt], ah0, ah1, ah2, ah3, bl0[nt], bl1[nt]);
                    mma16816(acc[mt][nt], al0, al1, al2, al3, bh0[nt], bh1[nt]);
                }
            }
        }
        __syncthreads();
    }
    // store V[j][b][n]
    #pragma unroll
    for (int mt = 0; mt < 2; ++mt) {
        #pragma unroll
        for (int nt = 0; nt < 4; ++nt) {
            int r0 = RM + mt * 16 + g, c = CN + nt * 8 + tq * 2;
            float* vp = d_V + ((size_t)j * BATCH + b0) * NB;
            *(float2*)(vp + (size_t)r0 * NB + c)       = make_float2(acc[mt][nt][0], acc[mt][nt][1]);
            *(float2*)(vp + (size_t)(r0 + 8) * NB + c) = make_float2(acc[mt][nt][2], acc[mt][nt][3]);
        }
    }
}

// ---------------- A1: sequential state scan (128 CTAs x 256, fp32) --------
__global__ void __launch_bounds__(256) ssm_a1() {
    __shared__ float MsT[4096], Xs[1024];
    const int tid = threadIdx.x;
    const int rowBase = blockIdx.x * 16;
    for (int i = tid; i < 4096; i += 256) MsT[i] = d_Mf[(i & 63) * 64 + (i >> 6)];
    for (int i = tid; i < 1024; i += 256) Xs[i] = 0.f;
    __syncthreads();
    const int nc = tid & 63, rg = tid >> 6;
    for (int j = 0; j < NCH; ++j) {
        for (int i = tid; i < 1024; i += 256)
            d_Xst[((size_t)j * BATCH + rowBase + (i >> 6)) * NB + (i & 63)] = Xs[i];
        if (j == NCH - 1) break;
        float a0 = 0, a1 = 0, a2 = 0, a3 = 0;
        #pragma unroll 8
        for (int n = 0; n < 64; ++n) {
            float m = MsT[n * 64 + nc];
            a0 += Xs[(rg * 4 + 0) * 64 + n] * m;
            a1 += Xs[(rg * 4 + 1) * 64 + n] * m;
            a2 += Xs[(rg * 4 + 2) * 64 + n] * m;
            a3 += Xs[(rg * 4 + 3) * 64 + n] * m;
        }
        const float* vp = d_V + ((size_t)j * BATCH + rowBase + rg * 4) * NB + nc;
        a0 += vp[0]; a1 += vp[64]; a2 += vp[128]; a3 += vp[192];
        __syncthreads();
        Xs[(rg * 4 + 0) * 64 + nc] = a0; Xs[(rg * 4 + 1) * 64 + nc] = a1;
        Xs[(rg * 4 + 2) * 64 + nc] = a2; Xs[(rg * 4 + 3) * 64 + nc] = a3;
        __syncthreads();
    }
}

// ---------------- B: Y = [X|U] * PbT  (1024 CTAs x 256, HMMA) --------------
// smem (bf16 units): AH 128x72, AL, BH 128x72, BL
#define B_AH 0
#define B_AL 9216
#define B_BH 18432
#define B_BL 27648
__global__ void __launch_bounds__(256) ssm_b(const float* __restrict__ u,
                                             float* __restrict__ y) {
    extern __shared__ __align__(16) __nv_bfloat16 smb[];
    uint32_t* sw = reinterpret_cast<uint32_t*>(smb);
    const int tid = threadIdx.x;
    const int j = blockIdx.x >> 4, b0 = (blockIdx.x & 15) << 7;
    const int wid = tid >> 5, lane = tid & 31;
    const int g = lane >> 2, tq = lane & 3;
    const int wm = wid >> 2, wn = wid & 3;          // 2x4 warp grid
    const int RM = wm * 64, CN = wn * 32;

    float acc[4][4][4];
    #pragma unroll
    for (int a = 0; a < 4; ++a)
        #pragma unroll
        for (int bq = 0; bq < 4; ++bq)
            #pragma unroll
            for (int cq = 0; cq < 4; ++cq) acc[a][bq][cq] = 0.f;

    for (int s = 0; s < 3; ++s) {
        // stage PbT slab: 128 t rows x 32 u32
        for (int i = tid; i < 4096; i += 256) {
            int t2 = i >> 5, c2 = i & 31;
            sw[(B_BH >> 1) + t2 * 36 + c2] = ((const uint32_t*)d_PbHi)[t2 * 96 + s * 32 + c2];
            sw[(B_BL >> 1) + t2 * 36 + c2] = ((const uint32_t*)d_PbLo)[t2 * 96 + s * 32 + c2];
        }
        // stage A slab (s=0: X, s>=1: U) hi/lo
        for (int i = tid; i < 2048; i += 256) {
            int r = i >> 4, c4 = (i & 15) * 4;
            float4 f;
            if (s == 0)
                f = *(const float4*)(d_Xst + ((size_t)j * BATCH + b0 + r) * NB + c4);
            else
                f = *(const float4*)(u + (size_t)(b0 + r) * L + j * QC + (s - 1) * 64 + c4);
            uint32_t h0, l0, h1, l1;
            splitpk(f.x, f.y, h0, l0); splitpk(f.z, f.w, h1, l1);
            int o = r * 36 + (c4 >> 1);
            sw[(B_AH >> 1) + o] = h0; sw[(B_AH >> 1) + o + 1] = h1;
            sw[(B_AL >> 1) + o] = l0; sw[(B_AL >> 1) + o + 1] = l1;
        }
        __syncthreads();
        #pragma unroll
        for (int kk = 0; kk < 64; kk += 16) {
            const int kb = (kk >> 1) + tq;
            uint32_t bh0[4], bh1[4], bl0[4], bl1[4];
            #pragma unroll
            for (int nt = 0; nt < 4; ++nt) {
                int n = CN + nt * 8 + g;
                bh0[nt] = sw[(B_BH >> 1) + n * 36 + kb];
                bh1[nt] = sw[(B_BH >> 1) + n * 36 + kb + 4];
                bl0[nt] = sw[(B_BL >> 1) + n * 36 + kb];
                bl1[nt] = sw[(B_BL >> 1) + n * 36 + kb + 4];
            }
            #pragma unroll
            for (int mt = 0; mt < 4; ++mt) {
                int r0 = RM + mt * 16 + g, r1 = r0 + 8;
                uint32_t ah0 = sw[(B_AH >> 1) + r0 * 36 + kb];
                uint32_t ah1 = sw[(B_AH >> 1) + r1 * 36 + kb];
                uint32_t ah2 = sw[(B_AH >> 1) + r0 * 36 + kb + 4];
                uint32_t ah3 = sw[(B_AH >> 1) + r1 * 36 + kb + 4];
                uint32_t al0 = sw[(B_AL >> 1) + r0 * 36 + kb];
                uint32_t al1 = sw[(B_AL >> 1) + r1 * 36 + kb];
                uint32_t al2 = sw[(B_AL >> 1) + r0 * 36 + kb + 4];
                uint32_t al3 = sw[(B_AL >> 1) + r1 * 36 + kb + 4];
                #pragma unroll
                for (int nt = 0; nt < 4; ++nt) {
                    mma16816(acc[mt][nt], ah0, ah1, ah2, ah3, bh0[nt], bh1[nt]);
                    mma16816(acc[mt][nt], ah0, ah1, ah2, ah3, bl0[nt], bl1[nt]);
                    mma16816(acc[mt][nt], al0, al1, al2, al3, bh0[nt], bh1[nt]);
                }
            }
        }
        __syncthreads();
    }
    // store Y: y[b0+row][j*128 + col]
    #pragma unroll
    for (int mt = 0; mt < 4; ++mt) {
        #pragma unroll
        for (int nt = 0; nt < 4; ++nt) {
            int r0 = RM + mt * 16 + g;
            int col = j * QC + CN + nt * 8 + tq * 2;
            *(float2*)(y + (size_t)(b0 + r0) * L + col)     = make_float2(acc[mt][nt][0], acc[mt][nt][1]);
            *(float2*)(y + (size_t)(b0 + r0 + 8) * L + col) = make_float2(acc[mt][nt][2], acc[mt][nt][3]);
        }
    }
}

extern "C" void kernel_launch(void* const* d_in, const int* in_sizes, int n_in,
                              void* d_out, int out_size) {
    const float* u  = (const float*)d_in[0];
    const float* A  = (const float*)d_in[1];
    const float* B  = (const float*)d_in[2];
    const float* C  = (const float*)d_in[3];
    const float* D  = (const float*)d_in[4];
    const float* ls = (const float*)d_in[5];
    float* y = (float*)d_out;

    const int smA0 = 27648 * 2;   // 55296 B
    const int smB  = 36864 * 2;   // 73728 B
    cudaFuncSetAttribute(ssm_a0, cudaFuncAttributeMaxDynamicSharedMemorySize, smA0);
    cudaFuncSetAttribute(ssm_b,  cudaFuncAttributeMaxDynamicSharedMemorySize, smB);

    ssm_gj<<<1, 256>>>(A, B, C, D, ls);
    ssm_mega<<<192, 64>>>();
    ssm_a0<<<1024, 256, smA0>>>(u);
    ssm_a1<<<128, 256>>>();
    ssm_b<<<1024, 256, smB>>>(u, y);
}

// round 9
// speedup vs baseline: 1.6761x; 1.0121x over previous
#include <cuda_runtime.h>
#include <cuda_bf16.h>
#include <cstdint>

#define NB    64          // state size
#define L     8192
#define BATCH 2048
#define QC    128         // chunk length
#define NCH   64          // chunks
#define KB    192         // 64 (X) + 128 (U)

// ---------------- constants built by setup ----------------
__device__ float d_Mf[NB * NB];                               // Ab^128
__device__ __nv_bfloat16 d_WHi[NB * QC],  d_WLo[NB * QC];     // WinT [n][i], pitch 128
__device__ __nv_bfloat16 d_PbHi[QC * KB], d_PbLo[QC * KB];    // PbT  [t][k], pitch 192
__device__ float d_V  [(size_t)NCH * BATCH * NB];             // V[j][b][n]
__device__ float d_Xst[(size_t)NCH * BATCH * NB];             // X[j][b][n]

// fp64 setup workspace
__device__ double d_T[NB * NB], d_R[NB * NB], d_X[NB * NB], d_X2[NB * NB];
__device__ double d_W[NB * NB], d_Ab[NB * NB], d_SA[NB * NB], d_SB[NB * NB];
__device__ double d_Rm[QC + 1][NB], d_Cm[QC][NB], d_Kk[QC];
__device__ double d_Cv[NB], d_Bv[NB], d_Dv, d_sp;
__device__ unsigned g_cnt = 0;
__device__ volatile unsigned g_gen = 0;

// ---------------- helpers ----------------
__device__ __forceinline__ void splitpk(float a, float b, uint32_t& hi, uint32_t& lo) {
    __nv_bfloat16 ha = __float2bfloat16(a), hb = __float2bfloat16(b);
    __nv_bfloat162 h, l;
    h.x = ha; h.y = hb;
    l.x = __float2bfloat16(a - __bfloat162float(ha));
    l.y = __float2bfloat16(b - __bfloat162float(hb));
    hi = *(uint32_t*)&h; lo = *(uint32_t*)&l;
}
__device__ __forceinline__ void mma16816(float* c, uint32_t a0, uint32_t a1,
                                         uint32_t a2, uint32_t a3,
                                         uint32_t b0, uint32_t b1) {
    asm volatile(
        "mma.sync.aligned.m16n8k16.row.col.f32.bf16.bf16.f32 "
        "{%0,%1,%2,%3}, {%4,%5,%6,%7}, {%8,%9}, {%0,%1,%2,%3};"
        : "+f"(c[0]), "+f"(c[1]), "+f"(c[2]), "+f"(c[3])
        : "r"(a0), "r"(a1), "r"(a2), "r"(a3), "r"(b0), "r"(b1));
}
// 4-chain fp64 row-dot: v (shared/local row) . S column t
__device__ __forceinline__ double dot64_row(const double* v, const double* S, int t) {
    double a0 = 0, a1 = 0, a2 = 0, a3 = 0;
    #pragma unroll 8
    for (int m = 0; m < 64; m += 4) {
        a0 += v[m]     * S[m * 64 + t];
        a1 += v[m + 1] * S[(m + 1) * 64 + t];
        a2 += v[m + 2] * S[(m + 2) * 64 + t];
        a3 += v[m + 3] * S[(m + 3) * 64 + t];
    }
    return (a0 + a1) + (a2 + a3);
}
__device__ __forceinline__ double dot64_col(const double* S, int t, const double* v) {
    double a0 = 0, a1 = 0, a2 = 0, a3 = 0;
    #pragma unroll 8
    for (int m = 0; m < 64; m += 4) {
        a0 += S[t * 64 + m]     * v[m];
        a1 += S[t * 64 + m + 1] * v[m + 1];
        a2 += S[t * 64 + m + 2] * v[m + 2];
        a3 += S[t * 64 + m + 3] * v[m + 3];
    }
    return (a0 + a1) + (a2 + a3);
}

// ---------------- L0: fp32 Gauss-Jordan seed + fp64 stash ----------------
__global__ void ssm_gj(const float* __restrict__ A, const float* __restrict__ B,
                       const float* __restrict__ C, const float* __restrict__ Dp,
                       const float* __restrict__ ls) {
    __shared__ float G[64 * 128];
    __shared__ float fac[64];
    const int tid = threadIdx.x, nt = 256;
    const double sd = exp((double)ls[0]);
    const float s = (float)sd;
    for (int i = tid; i < 4096; i += nt) {
        int r = i >> 6, c = i & 63;
        double a = (double)A[i];
        d_T[i] = (r == c ? 1.0 : 0.0) - 0.5 * sd * a;
        d_R[i] = (r == c ? 1.0 : 0.0) + 0.5 * sd * a;
    }
    for (int i = tid; i < 8192; i += nt) {
        int r = i >> 7, c = i & 127;
        G[i] = (c < 64) ? ((r == c ? 1.f : 0.f) - 0.5f * s * A[r * 64 + c])
                        : (((c - 64) == r) ? 1.f : 0.f);
    }
    if (tid < 64) { d_Cv[tid] = (double)C[tid]; d_Bv[tid] = (double)B[tid]; }
    if (tid == 0) { d_Dv = (double)Dp[0]; d_sp = sd; }
    __syncthreads();
    for (int p = 0; p < 64; ++p) {
        float pv = 1.f / G[p * 128 + p];
        __syncthreads();
        for (int c = tid; c < 128; c += nt) G[p * 128 + c] *= pv;
        for (int r = tid; r < 64; r += nt) fac[r] = G[r * 128 + p];
        __syncthreads();
        for (int i = tid; i < 8192; i += nt) {
            int r = i >> 7, c = i & 127;
            if (r != p) G[i] -= fac[r] * G[p * 128 + c];
        }
        __syncthreads();
    }
    for (int i = tid; i < 4096; i += nt)
        d_X[i] = (double)G[(i >> 6) * 128 + 64 + (i & 63)];
}

// ---------------- L1: mega setup (192 blocks x 64, grid barrier) ----------
__device__ __forceinline__ void gbar() {
    __syncthreads();
    if (threadIdx.x == 0) {
        __threadfence();
        unsigned g = g_gen;
        if (atomicAdd(&g_cnt, 1u) == 191u) { g_cnt = 0; __threadfence(); g_gen = g + 1; }
        else { while (g_gen == g) __nanosleep(64); __threadfence(); }
    }
    __syncthreads();
}
__global__ void ssm_mega() {
    __shared__ double v[64], red[64];
    const int b = blockIdx.x, t = threadIdx.x;
    if (b < 64) {                                  // W = X*T
        v[t] = d_X[b * 64 + t]; __syncthreads();
        d_W[b * 64 + t] = dot64_row(v, d_T, t);
    }
    gbar();
    if (b < 64) {                                  // X2 = 2X - W*X  (Newton)
        v[t] = d_W[b * 64 + t]; __syncthreads();
        d_X2[b * 64 + t] = 2.0 * d_X[b * 64 + t] - dot64_row(v, d_X, t);
    }
    gbar();
    if (b < 64) {                                  // Ab = X2*R
        v[t] = d_X2[b * 64 + t]; __syncthreads();
        d_Ab[b * 64 + t] = dot64_row(v, d_R, t);
    } else if (b == 64) {                          // Bb; seeds
        v[t] = d_Bv[t]; __syncthreads();
        d_Cm[0][t] = d_sp * dot64_col(d_X2, t, v);
        d_Rm[0][t] = d_Cv[t];
    }
    gbar();
    for (int lev = 0; lev < 7; ++lev) {            // chains + squaring to Ab^128
        int tw = 1 << lev;
        const double* S = (lev == 0) ? d_Ab : ((lev & 1) ? d_SA : d_SB);
        double* Sd = (lev & 1) ? d_SB : d_SA;
        if (b < tw) {                              // r_{t+tw} = r_t S
            v[t] = d_Rm[b][t]; __syncthreads();
            d_Rm[b + tw][t] = dot64_row(v, S, t);
        } else if (b < 2 * tw) {                   // c_{p+tw} = S c_p
            v[t] = d_Cm[b - tw][t]; __syncthreads();
            d_Cm[b][t] = dot64_col(S, t, v);
        } else if (b < 2 * tw + 64) {              // S' = S*S
            int r = b - 2 * tw;
            v[t] = S[r * 64 + t]; __syncthreads();
            Sd[r * 64 + t] = dot64_row(v, S, t);
        }
        gbar();
    }
    // M = Ab^128 lives in d_SA
    if (b < QC) {                                  // Kk[b] = C . c_b  (+D at 0)
        red[t] = d_Cv[t] * d_Cm[b][t]; __syncthreads();
        for (int o = 32; o > 0; o >>= 1) { if (t < o) red[t] += red[t + o]; __syncthreads(); }
        if (t == 0) d_Kk[b] = red[0] + ((b == 0) ? d_Dv : 0.0);
    } else if (b == QC) {                          // r_128 = C * M
        v[t] = d_Cv[t]; __syncthreads();
        d_Rm[QC][t] = dot64_row(v, d_SA, t);
    }
    gbar();
    const int gt = b * 64 + t, NT = 192 * 64;      // fills
    for (int i = gt; i < 4096; i += NT) d_Mf[i] = (float)d_SA[i];
    for (int i = gt; i < NB * QC; i += NT) {       // WinT[n][ii] = c_{127-ii}[n]
        int n = i >> 7, ii = i & 127;
        float f = (float)d_Cm[QC - 1 - ii][n];
        __nv_bfloat16 h = __float2bfloat16(f);
        d_WHi[i] = h; d_WLo[i] = __float2bfloat16(f - __bfloat162float(h));
    }
    for (int i = gt; i < QC * KB; i += NT) {       // PbT[t][k]
        int tt = i / KB, k = i % KB;
        double dv;
        if (k < 64) dv = d_Rm[tt + 1][k];
        else { int ii = k - 64; dv = (ii <= tt) ? d_Kk[tt - ii] : 0.0; }
        float f = (float)dv;
        __nv_bfloat16 h = __float2bfloat16(f);
        d_PbHi[i] = h; d_PbLo[i] = __float2bfloat16(f - __bfloat162float(h));
    }
}

// ---------------- A0: V = U * Win  (1024 CTAs x 256, HMMA) -----------------
// smem (bf16 units): AH 128x72, AL 128x72, BH 64x72, BL 64x72
#define A0_AH 0
#define A0_AL 9216
#define A0_BH 18432
#define A0_BL 23040
__global__ void __launch_bounds__(256) ssm_a0(const float* __restrict__ u) {
    extern __shared__ __align__(16) __nv_bfloat16 smb[];
    uint32_t* sw = reinterpret_cast<uint32_t*>(smb);
    const int tid = threadIdx.x;
    const int j = blockIdx.x >> 4, b0 = (blockIdx.x & 15) << 7;
    const int wid = tid >> 5, lane = tid & 31;
    const int g = lane >> 2, tq = lane & 3;
    const int wm = wid >> 1, wn = wid & 1;          // 4x2 warp grid
    const int RM = wm * 32, CN = wn * 32;

    float acc[2][4][4];
    #pragma unroll
    for (int a = 0; a < 2; ++a)
        #pragma unroll
        for (int bq = 0; bq < 4; ++bq)
            #pragma unroll
            for (int cq = 0; cq < 4; ++cq) acc[a][bq][cq] = 0.f;

    for (int s = 0; s < 2; ++s) {
        for (int i = tid; i < 2048; i += 256) {     // Win slab
            int n = i >> 5, c2 = i & 31;
            sw[(A0_BH >> 1) + n * 36 + c2] = ((const uint32_t*)d_WHi)[n * 64 + s * 32 + c2];
            sw[(A0_BL >> 1) + n * 36 + c2] = ((const uint32_t*)d_WLo)[n * 64 + s * 32 + c2];
        }
        for (int i = tid; i < 2048; i += 256) {     // U slab hi/lo
            int r = i >> 4, c4 = (i & 15) * 4;
            float4 f = *(const float4*)(u + (size_t)(b0 + r) * L + j * QC + s * 64 + c4);
            uint32_t h0, l0, h1, l1;
            splitpk(f.x, f.y, h0, l0); splitpk(f.z, f.w, h1, l1);
            int o = r * 36 + (c4 >> 1);
            sw[(A0_AH >> 1) + o] = h0; sw[(A0_AH >> 1) + o + 1] = h1;
            sw[(A0_AL >> 1) + o] = l0; sw[(A0_AL >> 1) + o + 1] = l1;
        }
        __syncthreads();
        #pragma unroll
        for (int kk = 0; kk < 64; kk += 16) {
            const int kb = (kk >> 1) + tq;
            uint32_t bh0[4], bh1[4], bl0[4], bl1[4];
            #pragma unroll
            for (int nt = 0; nt < 4; ++nt) {
                int n = CN + nt * 8 + g;
                bh0[nt] = sw[(A0_BH >> 1) + n * 36 + kb];
                bh1[nt] = sw[(A0_BH >> 1) + n * 36 + kb + 4];
                bl0[nt] = sw[(A0_BL >> 1) + n * 36 + kb];
                bl1[nt] = sw[(A0_BL >> 1) + n * 36 + kb + 4];
            }
            #pragma unroll
            for (int mt = 0; mt < 2; ++mt) {
                int r0 = RM + mt * 16 + g, r1 = r0 + 8;
                uint32_t ah0 = sw[(A0_AH >> 1) + r0 * 36 + kb];
                uint32_t ah1 = sw[(A0_AH >> 1) + r1 * 36 + kb];
                uint32_t ah2 = sw[(A0_AH >> 1) + r0 * 36 + kb + 4];
                uint32_t ah3 = sw[(A0_AH >> 1) + r1 * 36 + kb + 4];
                uint32_t al0 = sw[(A0_AL >> 1) + r0 * 36 + kb];
                uint32_t al1 = sw[(A0_AL >> 1) + r1 * 36 + kb];
                uint32_t al2 = sw[(A0_AL >> 1) + r0 * 36 + kb + 4];
                uint32_t al3 = sw[(A0_AL >> 1) + r1 * 36 + kb + 4];
                #pragma unroll
                for (int nt = 0; nt < 4; ++nt) {
                    mma16816(acc[mt][nt], ah0, ah1, ah2, ah3, bh0[nt], bh1[nt]);
                    mma16816(acc[mt][nt], ah0, ah1, ah2, ah3, bl0[nt], bl1[nt]);
                    mma16816(acc[mt][nt], al0, al1, al2, al3, bh0[nt], bh1[nt]);
                }
            }
        }
        __syncthreads();
    }
    #pragma unroll
    for (int mt = 0; mt < 2; ++mt) {
        #pragma unroll
        for (int nt = 0; nt < 4; ++nt) {
            int r0 = RM + mt * 16 + g, c = CN + nt * 8 + tq * 2;
            float* vp = d_V + ((size_t)j * BATCH + b0) * NB;
            *(float2*)(vp + (size_t)r0 * NB + c)       = make_float2(acc[mt][nt][0], acc[mt][nt][1]);
            *(float2*)(vp + (size_t)(r0 + 8) * NB + c) = make_float2(acc[mt][nt][2], acc[mt][nt][3]);
        }
    }
}

// ---------------- A1: sequential state scan (256 CTAs x 128, fp32) --------
// thread = 1 row x 4 cols.  Per n: 1 broadcast LDS (X) + 1 LDS.128 (M^T) + 4 FMA.
// V prefetched into accumulators before the FMA loop (hides global latency).
__global__ void __launch_bounds__(128) ssm_a1() {
    __shared__ float MsT[4096];      // [n][c] = Mf[c][n]
    __shared__ float Xs[8 * 64];     // [row][n]
    const int tid = threadIdx.x;
    const int rowBase = blockIdx.x * 8;
    for (int i = tid; i < 4096; i += 128) MsT[i] = d_Mf[(i & 63) * 64 + (i >> 6)];
    for (int i = tid; i < 512; i += 128) Xs[i] = 0.f;
    __syncthreads();
    const int row = tid >> 4, c0 = (tid & 15) * 4;
    float* xrow = Xs + row * 64;
    const size_t gstride = (size_t)BATCH * NB;
    float* xst = d_Xst + ((size_t)rowBase + row) * NB + c0;
    const float* vsrc = d_V + ((size_t)rowBase + row) * NB + c0;

    for (int j = 0; j < NCH; ++j) {
        *(float4*)(xst + (size_t)j * gstride) = *(float4*)(xrow + c0);   // store X_j
        if (j == NCH - 1) break;
        float4 vf = *(const float4*)(vsrc + (size_t)j * gstride);        // V_j prefetch
        float a0 = vf.x, a1 = vf.y, a2 = vf.z, a3 = vf.w;
        #pragma unroll 16
        for (int n = 0; n < 64; ++n) {
            float xv = xrow[n];
            float4 m = *(const float4*)(MsT + n * 64 + c0);
            a0 += xv * m.x; a1 += xv * m.y; a2 += xv * m.z; a3 += xv * m.w;
        }
        __syncthreads();
        *(float4*)(xrow + c0) = make_float4(a0, a1, a2, a3);
        __syncthreads();
    }
}

// ---------------- B: Y = [X|U] * PbT  (1024 CTAs x 256, HMMA) --------------
#define B_AH 0
#define B_AL 9216
#define B_BH 18432
#define B_BL 27648
__global__ void __launch_bounds__(256) ssm_b(const float* __restrict__ u,
                                             float* __restrict__ y) {
    extern __shared__ __align__(16) __nv_bfloat16 smb[];
    uint32_t* sw = reinterpret_cast<uint32_t*>(smb);
    const int tid = threadIdx.x;
    const int j = blockIdx.x >> 4, b0 = (blockIdx.x & 15) << 7;
    const int wid = tid >> 5, lane = tid & 31;
    const int g = lane >> 2, tq = lane & 3;
    const int wm = wid >> 2, wn = wid & 3;          // 2x4 warp grid
    const int RM = wm * 64, CN = wn * 32;

    float acc[4][4][4];
    #pragma unroll
    for (int a = 0; a < 4; ++a)
        #pragma unroll
        for (int bq = 0; bq < 4; ++bq)
            #pragma unroll
            for (int cq = 0; cq < 4; ++cq) acc[a][bq][cq] = 0.f;

    for (int s = 0; s < 3; ++s) {
        for (int i = tid; i < 4096; i += 256) {     // PbT slab
            int t2 = i >> 5, c2 = i & 31;
            sw[(B_BH >> 1) + t2 * 36 + c2] = ((const uint32_t*)d_PbHi)[t2 * 96 + s * 32 + c2];
            sw[(B_BL >> 1) + t2 * 36 + c2] = ((const uint32_t*)d_PbLo)[t2 * 96 + s * 32 + c2];
        }
        for (int i = tid; i < 2048; i += 256) {     // A slab (s=0: X, else U)
            int r = i >> 4, c4 = (i & 15) * 4;
            float4 f;
            if (s == 0)
                f = *(const float4*)(d_Xst + ((size_t)j * BATCH + b0 + r) * NB + c4);
            else
                f = *(const float4*)(u + (size_t)(b0 + r) * L + j * QC + (s - 1) * 64 + c4);
            uint32_t h0, l0, h1, l1;
            splitpk(f.x, f.y, h0, l0); splitpk(f.z, f.w, h1, l1);
            int o = r * 36 + (c4 >> 1);
            sw[(B_AH >> 1) + o] = h0; sw[(B_AH >> 1) + o + 1] = h1;
            sw[(B_AL >> 1) + o] = l0; sw[(B_AL >> 1) + o + 1] = l1;
        }
        __syncthreads();
        #pragma unroll
        for (int kk = 0; kk < 64; kk += 16) {
            const int kb = (kk >> 1) + tq;
            uint32_t bh0[4], bh1[4], bl0[4], bl1[4];
            #pragma unroll
            for (int nt = 0; nt < 4; ++nt) {
                int n = CN + nt * 8 + g;
                bh0[nt] = sw[(B_BH >> 1) + n * 36 + kb];
                bh1[nt] = sw[(B_BH >> 1) + n * 36 + kb + 4];
                bl0[nt] = sw[(B_BL >> 1) + n * 36 + kb];
                bl1[nt] = sw[(B_BL >> 1) + n * 36 + kb + 4];
            }
            #pragma unroll
            for (int mt = 0; mt < 4; ++mt) {
                int r0 = RM + mt * 16 + g, r1 = r0 + 8;
                uint32_t ah0 = sw[(B_AH >> 1) + r0 * 36 + kb];
                uint32_t ah1 = sw[(B_AH >> 1) + r1 * 36 + kb];
                uint32_t ah2 = sw[(B_AH >> 1) + r0 * 36 + kb + 4];
                uint32_t ah3 = sw[(B_AH >> 1) + r1 * 36 + kb + 4];
                uint32_t al0 = sw[(B_AL >> 1) + r0 * 36 + kb];
                uint32_t al1 = sw[(B_AL >> 1) + r1 * 36 + kb];
                uint32_t al2 = sw[(B_AL >> 1) + r0 * 36 + kb + 4];
                uint32_t al3 = sw[(B_AL >> 1) + r1 * 36 + kb + 4];
                #pragma unroll
                for (int nt = 0; nt < 4; ++nt) {
                    mma16816(acc[mt][nt], ah0, ah1, ah2, ah3, bh0[nt], bh1[nt]);
                    mma16816(acc[mt][nt], ah0, ah1, ah2, ah3, bl0[nt], bl1[nt]);
                    mma16816(acc[mt][nt], al0, al1, al2, al3, bh0[nt], bh1[nt]);
                }
            }
        }
        __syncthreads();
    }
    #pragma unroll
    for (int mt = 0; mt < 4; ++mt) {
        #pragma unroll
        for (int nt = 0; nt < 4; ++nt) {
            int r0 = RM + mt * 16 + g;
            int col = j * QC + CN + nt * 8 + tq * 2;
            *(float2*)(y + (size_t)(b0 + r0) * L + col)     = make_float2(acc[mt][nt][0], acc[mt][nt][1]);
            *(float2*)(y + (size_t)(b0 + r0 + 8) * L + col) = make_float2(acc[mt][nt][2], acc[mt][nt][3]);
        }
    }
}

extern "C" void kernel_launch(void* const* d_in, const int* in_sizes, int n_in,
                              void* d_out, int out_size) {
    const float* u  = (const float*)d_in[0];
    const float* A  = (const float*)d_in[1];
    const float* B  = (const float*)d_in[2];
    const float* C  = (const float*)d_in[3];
    const float* D  = (const float*)d_in[4];
    const float* ls = (const float*)d_in[5];
    float* y = (float*)d_out;

    const int smA0 = 27648 * 2;   // 55296 B
    const int smB  = 36864 * 2;   // 73728 B
    cudaFuncSetAttribute(ssm_a0, cudaFuncAttributeMaxDynamicSharedMemorySize, smA0);
    cudaFuncSetAttribute(ssm_b,  cudaFuncAttributeMaxDynamicSharedMemorySize, smB);

    ssm_gj<<<1, 256>>>(A, B, C, D, ls);
    ssm_mega<<<192, 64>>>();
    ssm_a0<<<1024, 256, smA0>>>(u);
    ssm_a1<<<256, 128>>>();
    ssm_b<<<1024, 256, smB>>>(u, y);
}